// round 5
// baseline (speedup 1.0000x reference)
#include <cuda_runtime.h>
#include <cstdint>

// BDToGEConverter: out[b,s,p,d] = sum_k W[p,d,k] * x[b,s,k], W fixed-sparse:
//   out[.,0,0]=Σ j·x[64+j]  out[.,0,1]=Σ j·x[96+j]
//   out[.,1,0]=Σ j·x[80+j]  out[.,1,1]=Σ j·x[112+j]       (j=0..15)
//   for all p: x10→d27 x11→d28 x12→d29 x13→d30 x14→d31 x15→d32
//              x16→d25 x17→d26 x18→d33 x19→d34 ; all else 0.
//
// R5: single-pass register-composed stores with DEFAULT (write-back) policy.
// Each lane selects its float4 chunk value inline (zero / opcode-vec / dots)
// — no zero-flood + overwrite double-write, no syncwarp. Default policy lets
// L2 (126MB) retain output lines across graph replays instead of forcing
// every byte to DRAM like .cs did.

static constexpr int BD_DIM   = 512;
static constexpr int ROW_OUT4 = 320;     // float4 per (b,s) row
static constexpr int THREADS  = 256;     // 8 warps = 8 rows per block

__global__ __launch_bounds__(THREADS)
void bd2ge_onepass(const float* __restrict__ x, float* __restrict__ out)
{
    const unsigned FULL = 0xffffffffu;
    const int t    = threadIdx.x;
    const int warp = t >> 5;
    const int lane = t & 31;

    const long long row = (long long)blockIdx.x * 8 + warp;
    const float*    g   = x + row * (long long)BD_DIM;

    // ---- per-lane input loads
    float a0 = 0.f, a1 = 0.f, a2 = 0.f, a3 = 0.f, vop = 0.f;
    if (lane < 16) {
        const float m = (float)lane;
        a0 = __ldg(g + 64  + lane) * m;
        a1 = __ldg(g + 80  + lane) * m;
        a2 = __ldg(g + 96  + lane) * m;
        a3 = __ldg(g + 112 + lane) * m;
    } else if (lane < 26) {
        vop = __ldg(g + 10 + (lane - 16));
    }

    // ---- reduce dots (lanes 0..15), then broadcast everything to all lanes
    #pragma unroll
    for (int o = 8; o > 0; o >>= 1) {
        a0 += __shfl_xor_sync(FULL, a0, o, 16);
        a1 += __shfl_xor_sync(FULL, a1, o, 16);
        a2 += __shfl_xor_sync(FULL, a2, o, 16);
        a3 += __shfl_xor_sync(FULL, a3, o, 16);
    }
    a0 = __shfl_sync(FULL, a0, 0);
    a1 = __shfl_sync(FULL, a1, 0);
    a2 = __shfl_sync(FULL, a2, 0);
    a3 = __shfl_sync(FULL, a3, 0);
    float xv[10];                        // xv[j] = x[10+j]
    #pragma unroll
    for (int j = 0; j < 10; ++j)
        xv[j] = __shfl_sync(FULL, vop, 16 + j);

    // chunk templates (per 40-float4 p-slice): chunk 6 -> d24..27,
    // chunk 7 -> d28..31, chunk 8 -> d32..35; chunk 0 of p0/p1 -> dot pairs
    const float4 Z  = make_float4(0.f, 0.f, 0.f, 0.f);
    const float4 S6 = make_float4(0.f,   xv[6], xv[7], xv[0]);
    const float4 S7 = make_float4(xv[1], xv[2], xv[3], xv[4]);
    const float4 S8 = make_float4(xv[5], xv[8], xv[9], 0.f);
    const float4 D0 = make_float4(a0, a2, 0.f, 0.f);
    const float4 D1 = make_float4(a1, a3, 0.f, 0.f);

    // ---- single composed pass: 10 float4 stores per lane, default policy
    float4* rowb = reinterpret_cast<float4*>(out) + row * (long long)ROW_OUT4;
    #pragma unroll
    for (int i = 0; i < 10; ++i) {
        const int c = i * 32 + lane;        // 0..319
        const int r = c % 40;               // position within p-slice
        float4 v = Z;
        if      (r == 6)  v = S6;
        else if (r == 7)  v = S7;
        else if (r == 8)  v = S8;
        if (c == 0)  v = D0;
        if (c == 40) v = D1;
        rowb[c] = v;                        // STG.E.128 write-back
    }
}

extern "C" void kernel_launch(void* const* d_in, const int* in_sizes, int n_in,
                              void* d_out, int out_size)
{
    const float* x = (const float*)d_in[0];   // x_bd [B,S,512]
    float* out = (float*)d_out;               // [B,S,8,160]

    int n_rows = in_sizes[0] / BD_DIM;        // B*S = 32768
    int grid   = n_rows / 8;                  // 4096 blocks, warp-per-row

    bd2ge_onepass<<<grid, THREADS>>>(x, out);
}

// round 9
// speedup vs baseline: 1.0127x; 1.0127x over previous
#include <cuda_runtime.h>
#include <cstdint>

// BDToGEConverter: out[b,s,p,d] = sum_k W[p,d,k] * x[b,s,k], W fixed-sparse
// (see prior rounds). R9 = R8 with plain __ldg input loads (sm_103 ptxas
// only allows L2 eviction hints on 256-bit ld/st; x loads are scalar).
// Stores: 256-bit v4.b64, first RES_ROWS rows evict_last (L2-resident
// across graph replays -> never drained to DRAM), rest evict_first.

static constexpr int BD_DIM    = 512;
static constexpr int ROW_BYTES = 5120;         // 1280 floats per (b,s) row
static constexpr int THREADS   = 256;          // 8 warps = 8 rows per block
static constexpr int RES_ROWS  = 17408;        // 17408*5120B = 89.1 MB resident

typedef unsigned long long u64;

__device__ __forceinline__ u64 pack2(float lo, float hi) {
    return (u64)__float_as_uint(lo) | ((u64)__float_as_uint(hi) << 32);
}

template<bool RES>
__device__ __forceinline__ void st256(char* p, u64 v0, u64 v1, u64 v2, u64 v3) {
    if (RES)
        asm volatile("st.global.L2::evict_last.v4.b64 [%0], {%1,%2,%3,%4};"
                     :: "l"(p), "l"(v0), "l"(v1), "l"(v2), "l"(v3) : "memory");
    else
        asm volatile("st.global.L2::evict_first.v4.b64 [%0], {%1,%2,%3,%4};"
                     :: "l"(p), "l"(v0), "l"(v1), "l"(v2), "l"(v3) : "memory");
}

template<bool RES>
__device__ __forceinline__ void emit_row(char* rowb, int lane,
                                         u64 d0, u64 d1,
                                         u64 s3a, u64 s3b, u64 s3c, u64 s3d,
                                         u64 s4a, u64 s4b)
{
    // ---- zero-flood: 5 x 32B per lane, immediate offsets (5120 B per row)
    char* pb = rowb + lane * 32;
    #pragma unroll
    for (int i = 0; i < 5; ++i)
        st256<RES>(pb + i * 1024, 0, 0, 0, 0);
    __syncwarp();

    // ---- 18 composed special chunks (each a full 32B v4.b64 store)
    if (lane == 0) {
        st256<RES>(rowb, d0, 0, 0, 0);                       // p0 d0..7
    } else if (lane == 1) {
        st256<RES>(rowb + 640, d1, 0, 0, 0);                 // p1 d0..7
    } else if (lane < 10) {                                  // p-slice chunk 3: d24..31
        st256<RES>(rowb + (lane - 2) * 640 + 96, s3a, s3b, s3c, s3d);
    } else if (lane < 18) {                                  // p-slice chunk 4: d32..39
        st256<RES>(rowb + (lane - 10) * 640 + 128, s4a, s4b, 0, 0);
    }
}

__global__ __launch_bounds__(THREADS)
void bd2ge_hint(const float* __restrict__ x, float* __restrict__ out)
{
    const unsigned FULL = 0xffffffffu;
    const int t    = threadIdx.x;
    const int warp = t >> 5;
    const int lane = t & 31;

    const long long row = (long long)blockIdx.x * 8 + warp;
    const float*    g   = x + row * (long long)BD_DIM;

    // ---- per-lane input loads (plain non-coherent loads)
    float a0 = 0.f, a1 = 0.f, a2 = 0.f, a3 = 0.f, vop = 0.f;
    if (lane < 16) {
        const float m = (float)lane;
        a0 = __ldg(g + 64  + lane) * m;
        a1 = __ldg(g + 80  + lane) * m;
        a2 = __ldg(g + 96  + lane) * m;
        a3 = __ldg(g + 112 + lane) * m;
    } else if (lane < 26) {
        vop = __ldg(g + 10 + (lane - 16));
    }

    // ---- dot reductions + broadcasts
    #pragma unroll
    for (int o = 8; o > 0; o >>= 1) {
        a0 += __shfl_xor_sync(FULL, a0, o, 16);
        a1 += __shfl_xor_sync(FULL, a1, o, 16);
        a2 += __shfl_xor_sync(FULL, a2, o, 16);
        a3 += __shfl_xor_sync(FULL, a3, o, 16);
    }
    a0 = __shfl_sync(FULL, a0, 0);
    a1 = __shfl_sync(FULL, a1, 0);
    a2 = __shfl_sync(FULL, a2, 0);
    a3 = __shfl_sync(FULL, a3, 0);
    float xv[10];                        // xv[j] = x[10+j]
    #pragma unroll
    for (int j = 0; j < 10; ++j)
        xv[j] = __shfl_sync(FULL, vop, 16 + j);

    // packed chunk payloads
    const u64 d0  = pack2(a0, a2);                  // p0: d0,d1
    const u64 d1  = pack2(a1, a3);                  // p1: d0,d1
    const u64 s3a = pack2(0.f,  xv[6]);             // d24=0, d25=x16
    const u64 s3b = pack2(xv[7], xv[0]);            // d26=x17, d27=x10
    const u64 s3c = pack2(xv[1], xv[2]);            // d28, d29
    const u64 s3d = pack2(xv[3], xv[4]);            // d30, d31
    const u64 s4a = pack2(xv[5], xv[8]);            // d32, d33
    const u64 s4b = pack2(xv[9], 0.f);              // d34, d35=0

    char* rowb = reinterpret_cast<char*>(out) + row * (long long)ROW_BYTES;
    if (row < RES_ROWS)
        emit_row<true >(rowb, lane, d0, d1, s3a, s3b, s3c, s3d, s4a, s4b);
    else
        emit_row<false>(rowb, lane, d0, d1, s3a, s3b, s3c, s3d, s4a, s4b);
}

extern "C" void kernel_launch(void* const* d_in, const int* in_sizes, int n_in,
                              void* d_out, int out_size)
{
    const float* x = (const float*)d_in[0];   // x_bd [B,S,512]
    float* out = (float*)d_out;               // [B,S,8,160]

    int n_rows = in_sizes[0] / BD_DIM;        // B*S = 32768
    int grid   = n_rows / 8;                  // 4096 blocks, warp-per-row

    bd2ge_hint<<<grid, THREADS>>>(x, out);
}